// round 5
// baseline (speedup 1.0000x reference)
#include <cuda_runtime.h>
#include <math.h>

// ---------------------------------------------------------------------------
// Problem constants
// ---------------------------------------------------------------------------
static constexpr int B   = 4;
static constexpr int L   = 5;
static constexpr int NL  = B * L;      // 20 images
static constexpr int C   = 64;
static constexpr int H   = 256;
static constexpr int W   = 128;
static constexpr int HW  = H * W;

static constexpr int C1O = 32, H1 = 128, W1 = 64;
static constexpr int C2O = 64, H2 = 64,  W2 = 32;
static constexpr int C3O = 64, H3 = 32,  W3 = 16;
static constexpr int KSPLIT3 = 4;

// ---------------------------------------------------------------------------
// Scratch (device globals)
// ---------------------------------------------------------------------------
__device__ float g_neigh[NL * C * H * W];            // ~168 MB
__device__ float g_c1[NL * C1O * H1 * W1];           // ~21 MB
__device__ float g_c2[NL * C2O * H2 * W2];           // ~10 MB
__device__ float g_c3p[KSPLIT3 * NL * C3O * H3 * W3];// partial sums
__device__ float g_wt1[C   * 16 * C1O * 2];          // duplicated-pair weights
__device__ float g_wt2[C1O * 16 * C2O * 2];
__device__ float g_wt3[C2O * 16 * C3O * 2];
__device__ float g_attn[NL];

// ---------------------------------------------------------------------------
// f32x2 packed-FMA helpers
// ---------------------------------------------------------------------------
__device__ __forceinline__ unsigned long long pk2(float lo, float hi) {
    unsigned long long r;
    asm("mov.b64 %0, {%1, %2};" : "=l"(r) : "f"(lo), "f"(hi));
    return r;
}
__device__ __forceinline__ void fma2(unsigned long long& d,
                                     unsigned long long a,
                                     unsigned long long b) {
    asm("fma.rn.f32x2 %0, %1, %2, %0;" : "+l"(d) : "l"(a), "l"(b));
}
__device__ __forceinline__ float2 up2(unsigned long long v) {
    float2 f;
    asm("mov.b64 {%0, %1}, %2;" : "=f"(f.x), "=f"(f.y) : "l"(v));
    return f;
}

// ---------------------------------------------------------------------------
// 0) Weight transpose+duplicate: [COUT][CIN][16] -> [CIN][16][COUT][2]
// ---------------------------------------------------------------------------
static constexpr int NW1 = C   * C1O * 16;   // 32768
static constexpr int NW2 = C1O * C2O * 16;   // 32768
static constexpr int NW3 = C2O * C3O * 16;   // 65536

__global__ void wtr_k(const float* __restrict__ w1,
                      const float* __restrict__ w2,
                      const float* __restrict__ w3)
{
    int i = blockIdx.x * 256 + threadIdx.x;
    if (i < NW1) {
        int co = i / (C * 16); int rr = i % (C * 16);
        int c = rr / 16, k = rr % 16;
        float v = w1[i];
        int o = ((c * 16 + k) * C1O + co) * 2;
        g_wt1[o] = v; g_wt1[o + 1] = v;
    } else if (i < NW1 + NW2) {
        int j = i - NW1;
        int co = j / (C1O * 16); int rr = j % (C1O * 16);
        int c = rr / 16, k = rr % 16;
        float v = w2[j];
        int o = ((c * 16 + k) * C2O + co) * 2;
        g_wt2[o] = v; g_wt2[o + 1] = v;
    } else if (i < NW1 + NW2 + NW3) {
        int j = i - NW1 - NW2;
        int co = j / (C2O * 16); int rr = j % (C2O * 16);
        int c = rr / 16, k = rr % 16;
        float v = w3[j];
        int o = ((c * 16 + k) * C3O + co) * 2;
        g_wt3[o] = v; g_wt3[o + 1] = v;
    }
}

// ---------------------------------------------------------------------------
// 1) Affine grid + bilinear sample
// ---------------------------------------------------------------------------
__global__ void sample_k(const float* __restrict__ x,
                         const float* __restrict__ nam)
{
    int idx = blockIdx.x * 256 + threadIdx.x;
    if (idx >= NL * HW) return;
    int w = idx % W;
    int h = (idx / W) % H;
    int n = idx / HW;
    int b = n / L, l = n % L;

    const float* t = nam + (size_t)(b * L * L + l) * 6;
    float gx = (w + 0.5f) * (2.0f / W) - 1.0f;
    float gy = (h + 0.5f) * (2.0f / H) - 1.0f;
    float u = t[0] * gx + t[1] * gy + t[2];
    float v = t[3] * gx + t[4] * gy + t[5];

    float xf = ((u + 1.0f) * (float)W - 1.0f) * 0.5f;
    float yf = ((v + 1.0f) * (float)H - 1.0f) * 0.5f;
    float x0f = floorf(xf), y0f = floorf(yf);
    float wx1 = xf - x0f, wy1 = yf - y0f;
    float wx0 = 1.0f - wx1, wy0 = 1.0f - wy1;
    int x0 = (int)x0f, y0 = (int)y0f;
    int x1 = x0 + 1,  y1 = y0 + 1;

    bool vx0 = (x0 >= 0) && (x0 < W), vx1 = (x1 >= 0) && (x1 < W);
    bool vy0 = (y0 >= 0) && (y0 < H), vy1 = (y1 >= 0) && (y1 < H);
    int cx0 = min(max(x0, 0), W - 1), cx1 = min(max(x1, 0), W - 1);
    int cy0 = min(max(y0, 0), H - 1), cy1 = min(max(y1, 0), H - 1);

    float w00 = wx0 * wy0 * ((vx0 && vy0) ? 1.0f : 0.0f);
    float w10 = wx1 * wy0 * ((vx1 && vy0) ? 1.0f : 0.0f);
    float w01 = wx0 * wy1 * ((vx0 && vy1) ? 1.0f : 0.0f);
    float w11 = wx1 * wy1 * ((vx1 && vy1) ? 1.0f : 0.0f);

    int o00 = cy0 * W + cx0, o10 = cy0 * W + cx1;
    int o01 = cy1 * W + cx0, o11 = cy1 * W + cx1;

    const float* ip = x + (size_t)n * C * HW;
    float* op = g_neigh + (size_t)n * C * HW + h * W + w;
#pragma unroll 4
    for (int c = 0; c < C; c++) {
        const float* pc = ip + (size_t)c * HW;
        float val = pc[o00] * w00 + pc[o10] * w10 + pc[o01] * w01 + pc[o11] * w11;
        op[(size_t)c * HW] = val;
    }
}

// ---------------------------------------------------------------------------
// 2) Direct conv 4x4 stride-2 pad-1, packed f32x2 FMA, smem-tiled.
//    Weights in smem pre-duplicated: [CC][16][COUT][2] -> LDS.64 gives the
//    packed (w,w) operand directly; no MOV packing for weights.
// ---------------------------------------------------------------------------
template<int CIN_ALL, int CINBLK, int COUT, int IH, int IW, int OH, int OW,
         int TOH, int TOW, int CC, int COT, int PPT, bool RELU, int NSPLIT>
__global__ void __launch_bounds__((TOH * TOW / PPT) * (COUT / COT))
conv_k(const float* __restrict__ in, const float* __restrict__ wgt,
       const float* __restrict__ bias, float* __restrict__ out)
{
    constexpr int ITH   = 2 * TOH + 2;
    constexpr int ITW   = 2 * TOW + 2;
    constexpr int ITWP  = (ITW + 3) & ~3;
    constexpr int PGRP  = TOH * TOW / PPT;
    constexpr int NGRP  = COUT / COT;
    constexpr int NT    = PGRP * NGRP;
    constexpr int NPAIR = PPT / 2;
    constexpr int NV4   = (2 * PPT + 2 + 3) / 4;

    extern __shared__ float sm[];
    float* s_in = sm;                               // [CC][ITH][ITWP]
    float* s_w  = sm + CC * ITH * ITWP;             // [CC][16][COUT][2]

    const int bz    = blockIdx.z;
    const int n     = bz / NSPLIT;
    const int split = bz % NSPLIT;
    const int cbase = split * CINBLK;
    const int oh0   = blockIdx.y * TOH;
    const int ow0   = blockIdx.x * TOW;
    const int tid   = threadIdx.x;
    const int pg    = tid % PGRP;
    const int cg    = tid / PGRP;
    const int co0   = cg * COT;
    const int pos0  = pg * PPT;
    const int ohl   = pos0 / TOW;
    const int owb   = pos0 % TOW;

    unsigned long long acc[COT][NPAIR];
#pragma unroll
    for (int a = 0; a < COT; a++)
#pragma unroll
        for (int p = 0; p < NPAIR; p++) acc[a][p] = 0ull;

    for (int c0 = 0; c0 < CINBLK; c0 += CC) {
        __syncthreads();
        // fill input tile (zero-pad OOB)
        for (int i = tid; i < CC * ITH * ITW; i += NT) {
            int c   = i / (ITH * ITW);
            int rem = i % (ITH * ITW);
            int r   = rem / ITW;
            int col = rem % ITW;
            int ih = oh0 * 2 - 1 + r;
            int iw = ow0 * 2 - 1 + col;
            float v = 0.0f;
            if (ih >= 0 && ih < IH && iw >= 0 && iw < IW)
                v = in[((size_t)(n * CIN_ALL + cbase + c0 + c) * IH + ih) * IW + iw];
            s_in[(c * ITH + r) * ITWP + col] = v;
        }
        // fill duplicated weight chunk (contiguous, float4)
        {
            const float4* wsrc =
                (const float4*)(wgt + (size_t)(cbase + c0) * 16 * COUT * 2);
            float4* wdst = (float4*)s_w;
            for (int i = tid; i < CC * 16 * COUT * 2 / 4; i += NT)
                wdst[i] = wsrc[i];
        }
        __syncthreads();

#pragma unroll 1
        for (int c = 0; c < CC; c++) {
            const float* srow = s_in + c * ITH * ITWP;
            const unsigned long long* swc =
                (const unsigned long long*)s_w + (c * 16) * COUT;
#pragma unroll
            for (int kh = 0; kh < 4; kh++) {
                float rvf[NV4 * 4];
                const float4* rp =
                    (const float4*)(srow + (ohl * 2 + kh) * ITWP + owb * 2);
#pragma unroll
                for (int j = 0; j < NV4; j++) {
                    float4 t = rp[j];
                    rvf[4 * j + 0] = t.x; rvf[4 * j + 1] = t.y;
                    rvf[4 * j + 2] = t.z; rvf[4 * j + 3] = t.w;
                }
#pragma unroll
                for (int kw = 0; kw < 4; kw++) {
                    unsigned long long ivp[NPAIR];
#pragma unroll
                    for (int p = 0; p < NPAIR; p++)
                        ivp[p] = pk2(rvf[4 * p + kw], rvf[4 * p + kw + 2]);
                    const unsigned long long* swk = swc + (kh * 4 + kw) * COUT + co0;
#pragma unroll
                    for (int a = 0; a < COT; a++) {
                        unsigned long long wd = swk[a];   // LDS.64 (w,w) pair
#pragma unroll
                        for (int p = 0; p < NPAIR; p++)
                            fma2(acc[a][p], wd, ivp[p]);
                    }
                }
            }
        }
    }

    const int oh = oh0 + ohl;
#pragma unroll
    for (int a = 0; a < COT; a++) {
        const int co = co0 + a;
        float bb = RELU ? bias[co] : 0.0f;
#pragma unroll
        for (int p = 0; p < NPAIR; p++) {
            float2 v = up2(acc[a][p]);
            size_t idx;
            if (RELU) {
                v.x = fmaxf(v.x + bb, 0.0f);
                v.y = fmaxf(v.y + bb, 0.0f);
                idx = ((size_t)(n * COUT + co) * OH + oh) * OW + ow0 + owb + 2 * p;
            } else {
                idx = ((size_t)((split * NL + n) * COUT + co) * OH + oh) * OW
                      + ow0 + owb + 2 * p;
            }
            *(float2*)&out[idx] = v;
        }
    }
}

// ---------------------------------------------------------------------------
// 3) Fused head: conv3-combine + bias + relu + pool, both MLP heads,
//    attention logits + softmax. Single block, smem-resident activations.
// ---------------------------------------------------------------------------
__global__ void __launch_bounds__(1024) head_k(
    const float* __restrict__ b3,
    const float* __restrict__ kf1w, const float* __restrict__ kf1b,
    const float* __restrict__ kf2w, const float* __restrict__ kf2b,
    const float* __restrict__ kf3w, const float* __restrict__ kf3b,
    const float* __restrict__ qf1w, const float* __restrict__ qf1b,
    const float* __restrict__ qf2w, const float* __restrict__ qf2b,
    const float* __restrict__ qf3w, const float* __restrict__ qf3b,
    const float* __restrict__ aw,   const float* __restrict__ ab)
{
    __shared__ float sp[NL * 64];      // pooled features
    __shared__ float sh1[NL * 256];    // key fc1 out; later reused for keys
    __shared__ float sh2[NL * 128];    // key fc2 out
    __shared__ float sq1[B * 256];
    __shared__ float sq2[B * 128];
    __shared__ float sqr[B * 32];
    __shared__ float sq[B * 256];
    __shared__ float lg[NL];

    const int tid = threadIdx.x, lane = tid & 31, wid = tid >> 5;
    constexpr size_t SP = (size_t)NL * 64 * 512;

    // pool: combine conv3 K-split partials + bias + relu + mean
    for (int pair = wid; pair < NL * 64; pair += 32) {
        const float* p = g_c3p + (size_t)pair * 512;
        float bb = b3[pair % 64];
        float s = 0.0f;
        for (int i = lane; i < 512; i += 32) {
            float v = p[i] + p[i + SP] + p[i + 2 * SP] + p[i + 3 * SP] + bb;
            s += fmaxf(v, 0.0f);
        }
#pragma unroll
        for (int o = 16; o; o >>= 1) s += __shfl_xor_sync(0xffffffffu, s, o);
        if (lane == 0) sp[pair] = s * (1.0f / 512.0f);
    }
    __syncthreads();

    // fc1: keys (20x256, in 64) and query (4x256, in 64)
    for (int g = tid; g < NL * 256; g += 1024) {
        int r = g >> 8, o = g & 255;
        const float* xr = sp + r * 64;
        const float* wr = kf1w + o * 64;
        float s = kf1b[o];
#pragma unroll 8
        for (int i = 0; i < 64; i++) s = fmaf(xr[i], wr[i], s);
        sh1[g] = fmaxf(s, 0.0f);
    }
    for (int g = tid; g < B * 256; g += 1024) {
        int r = g >> 8, o = g & 255;
        const float* xr = sp + (r * L) * 64;
        const float* wr = qf1w + o * 64;
        float s = qf1b[o];
#pragma unroll 8
        for (int i = 0; i < 64; i++) s = fmaf(xr[i], wr[i], s);
        sq1[g] = fmaxf(s, 0.0f);
    }
    __syncthreads();

    // fc2: (20x128, in 256) and (4x128, in 256)
    for (int g = tid; g < NL * 128; g += 1024) {
        int r = g >> 7, o = g & 127;
        const float* xr = sh1 + r * 256;
        const float* wr = kf2w + o * 256;
        float s = kf2b[o];
#pragma unroll 8
        for (int i = 0; i < 256; i++) s = fmaf(xr[i], wr[i], s);
        sh2[g] = fmaxf(s, 0.0f);
    }
    for (int g = tid; g < B * 128; g += 1024) {
        int r = g >> 7, o = g & 127;
        const float* xr = sq1 + r * 256;
        const float* wr = qf2w + o * 256;
        float s = qf2b[o];
#pragma unroll 8
        for (int i = 0; i < 256; i++) s = fmaf(xr[i], wr[i], s);
        sq2[g] = fmaxf(s, 0.0f);
    }
    __syncthreads();

    // fc3: keys (20x256, in 128) into sh1 (reuse); qry (4x32, in 128)
    for (int g = tid; g < NL * 256; g += 1024) {
        int r = g >> 8, o = g & 255;
        const float* xr = sh2 + r * 128;
        const float* wr = kf3w + o * 128;
        float s = kf3b[o];
#pragma unroll 8
        for (int i = 0; i < 128; i++) s = fmaf(xr[i], wr[i], s);
        sh1[g] = s;
    }
    for (int g = tid; g < B * 32; g += 1024) {
        int r = g >> 5, o = g & 31;
        const float* xr = sq2 + r * 128;
        const float* wr = qf3w + o * 128;
        float s = qf3b[o];
#pragma unroll 8
        for (int i = 0; i < 128; i++) s = fmaf(xr[i], wr[i], s);
        sqr[g] = s;
    }
    __syncthreads();

    // q = qry @ attn_w^T + attn_b : (4x256, in 32)
    for (int g = tid; g < B * 256; g += 1024) {
        int r = g >> 8, o = g & 255;
        const float* xr = sqr + r * 32;
        const float* wr = aw + o * 32;
        float s = ab[o];
#pragma unroll 8
        for (int i = 0; i < 32; i++) s = fmaf(xr[i], wr[i], s);
        sq[g] = s;
    }
    __syncthreads();

    // logits: one warp per (b, l)
    if (wid < NL) {
        const float* k = sh1 + wid * 256;
        const float* q = sq + (wid / L) * 256;
        float s = 0.0f;
        for (int i = lane; i < 256; i += 32) s = fmaf(k[i], q[i], s);
#pragma unroll
        for (int o = 16; o; o >>= 1) s += __shfl_xor_sync(0xffffffffu, s, o);
        if (lane == 0) lg[wid] = s;
    }
    __syncthreads();

    // softmax over L per batch
    if (tid < B) {
        float m = lg[tid * L];
#pragma unroll
        for (int l = 1; l < L; l++) m = fmaxf(m, lg[tid * L + l]);
        float e[L], sum = 0.0f;
#pragma unroll
        for (int l = 0; l < L; l++) { e[l] = expf(lg[tid * L + l] - m); sum += e[l]; }
        float inv = 1.0f / sum;
#pragma unroll
        for (int l = 0; l < L; l++) g_attn[tid * L + l] = e[l] * inv;
    }
}

// ---------------------------------------------------------------------------
// 4) Fusion (float4 vectorized)
// ---------------------------------------------------------------------------
__global__ void fuse_k(float* __restrict__ out)
{
    int idx = blockIdx.x * 256 + threadIdx.x;       // float4 index
    constexpr int TOT = B * C * HW / 4;
    if (idx >= TOT) return;
    int b = idx / (C * HW / 4);
    int rem = idx - b * (C * HW / 4);
    const float4* np = (const float4*)(g_neigh + (size_t)b * L * C * HW) + rem;
    float4 s = make_float4(0.f, 0.f, 0.f, 0.f);
#pragma unroll
    for (int l = 0; l < L; l++) {
        float a = g_attn[b * L + l];
        float4 v = np[(size_t)l * (C * HW / 4)];
        s.x = fmaf(a, v.x, s.x); s.y = fmaf(a, v.y, s.y);
        s.z = fmaf(a, v.z, s.z); s.w = fmaf(a, v.w, s.w);
    }
    ((float4*)out)[idx] = s;
}

// ---------------------------------------------------------------------------
// Launch
// ---------------------------------------------------------------------------
extern "C" void kernel_launch(void* const* d_in, const int* in_sizes, int n_in,
                              void* d_out, int out_size)
{
    (void)in_sizes; (void)n_in; (void)out_size;
    const float* x    = (const float*)d_in[0];
    const float* nam  = (const float*)d_in[2];
    const float* w1   = (const float*)d_in[3];
    const float* b1   = (const float*)d_in[4];
    const float* w2   = (const float*)d_in[5];
    const float* b2   = (const float*)d_in[6];
    const float* w3   = (const float*)d_in[7];
    const float* b3   = (const float*)d_in[8];
    const float* kf1w = (const float*)d_in[9];
    const float* kf1b = (const float*)d_in[10];
    const float* kf2w = (const float*)d_in[11];
    const float* kf2b = (const float*)d_in[12];
    const float* kf3w = (const float*)d_in[13];
    const float* kf3b = (const float*)d_in[14];
    const float* qf1w = (const float*)d_in[15];
    const float* qf1b = (const float*)d_in[16];
    const float* qf2w = (const float*)d_in[17];
    const float* qf2b = (const float*)d_in[18];
    const float* qf3w = (const float*)d_in[19];
    const float* qf3b = (const float*)d_in[20];
    const float* aw   = (const float*)d_in[21];
    const float* ab   = (const float*)d_in[22];
    float* out = (float*)d_out;

    float *p_neigh, *p_c1, *p_c2, *p_c3p, *p_wt1, *p_wt2, *p_wt3;
    cudaGetSymbolAddress((void**)&p_neigh, g_neigh);
    cudaGetSymbolAddress((void**)&p_c1,   g_c1);
    cudaGetSymbolAddress((void**)&p_c2,   g_c2);
    cudaGetSymbolAddress((void**)&p_c3p,  g_c3p);
    cudaGetSymbolAddress((void**)&p_wt1,  g_wt1);
    cudaGetSymbolAddress((void**)&p_wt2,  g_wt2);
    cudaGetSymbolAddress((void**)&p_wt3,  g_wt3);

    // conv kernel instantiations
    auto c1 = conv_k<64, 64, 32, 256, 128, 128, 64, 16, 16, 8, 8, 8, true, 1>;
    auto c2 = conv_k<32, 32, 64, 128, 64, 64, 32, 8, 8, 4, 4, 8, true, 1>;
    auto c3 = conv_k<64, 16, 64, 64, 32, 32, 16, 4, 16, 8, 4, 8, false, KSPLIT3>;
    const int sm1 = (8 * 34 * 36 + 8 * 16 * 32 * 2) * 4;   // 71936
    const int sm2 = (4 * 18 * 20 + 4 * 16 * 64 * 2) * 4;   // 38528
    const int sm3 = (8 * 10 * 36 + 8 * 16 * 64 * 2) * 4;   // 77056
    cudaFuncSetAttribute(c1, cudaFuncAttributeMaxDynamicSharedMemorySize, sm1);
    cudaFuncSetAttribute(c2, cudaFuncAttributeMaxDynamicSharedMemorySize, sm2);
    cudaFuncSetAttribute(c3, cudaFuncAttributeMaxDynamicSharedMemorySize, sm3);

    // 0) weight transpose+duplicate
    wtr_k<<<(NW1 + NW2 + NW3 + 255) / 256, 256>>>(w1, w2, w3);

    // 1) grid sample
    sample_k<<<(NL * HW + 255) / 256, 256>>>(x, nam);

    // 2) conv pyramid
    c1<<<dim3(W1 / 16, H1 / 16, NL), 128, sm1>>>(p_neigh, p_wt1, b1, p_c1);
    c2<<<dim3(W2 / 8,  H2 / 8,  NL), 128, sm2>>>(p_c1,    p_wt2, b2, p_c2);
    c3<<<dim3(W3 / 16, H3 / 4,  NL * KSPLIT3), 128, sm3>>>(p_c2, p_wt3, b3, p_c3p);

    // 3) fused head (pool + MLPs + attention softmax)
    head_k<<<1, 1024>>>(b3, kf1w, kf1b, kf2w, kf2b, kf3w, kf3b,
                        qf1w, qf1b, qf2w, qf2b, qf3w, qf3b, aw, ab);

    // 4) fuse
    fuse_k<<<(B * C * HW / 4 + 255) / 256, 256>>>(out);
}

// round 6
// speedup vs baseline: 2.0972x; 2.0972x over previous
#include <cuda_runtime.h>
#include <math.h>

// ---------------------------------------------------------------------------
// Problem constants
// ---------------------------------------------------------------------------
static constexpr int B   = 4;
static constexpr int L   = 5;
static constexpr int NL  = B * L;      // 20 images
static constexpr int C   = 64;
static constexpr int H   = 256;
static constexpr int W   = 128;
static constexpr int HW  = H * W;

static constexpr int C1O = 32, H1 = 128, W1 = 64;
static constexpr int C2O = 64, H2 = 64,  W2 = 32;
static constexpr int C3O = 64, H3 = 32,  W3 = 16;
static constexpr int KSPLIT3 = 4;

// ---------------------------------------------------------------------------
// Scratch (device globals)
// ---------------------------------------------------------------------------
__device__ float g_neigh[NL * C * H * W];            // ~168 MB
__device__ float g_c1[NL * C1O * H1 * W1];           // ~21 MB
__device__ float g_c2[NL * C2O * H2 * W2];           // ~10 MB
__device__ float g_c3p[KSPLIT3 * NL * C3O * H3 * W3];// partial sums
__device__ float g_wt1[C * 16 * C1O];                // transposed weights
__device__ float g_wt2[C1O * 16 * C2O];
__device__ float g_wt3[C2O * 16 * C3O];
__device__ float g_pool[NL * 64];
__device__ float g_h1[NL * 256];
__device__ float g_h2[NL * 128];
__device__ float g_keys[NL * 256];
__device__ float g_qh1[B * 256];
__device__ float g_qh2[B * 128];
__device__ float g_qry[B * 32];
__device__ float g_q[B * 256];
__device__ float g_attn[NL];

// ---------------------------------------------------------------------------
// f32x2 packed-FMA helpers (Blackwell FFMA2 path, PTX-only)
// ---------------------------------------------------------------------------
__device__ __forceinline__ unsigned long long pk2(float lo, float hi) {
    unsigned long long r;
    asm("mov.b64 %0, {%1, %2};" : "=l"(r) : "f"(lo), "f"(hi));
    return r;
}
__device__ __forceinline__ void fma2(unsigned long long& d,
                                     unsigned long long a,
                                     unsigned long long b) {
    asm("fma.rn.f32x2 %0, %1, %2, %0;" : "+l"(d) : "l"(a), "l"(b));
}
__device__ __forceinline__ float2 up2(unsigned long long v) {
    float2 f;
    asm("mov.b64 {%0, %1}, %2;" : "=f"(f.x), "=f"(f.y) : "l"(v));
    return f;
}

// ---------------------------------------------------------------------------
// 1) Affine grid + bilinear sample
// ---------------------------------------------------------------------------
__global__ void sample_k(const float* __restrict__ x,
                         const float* __restrict__ nam)
{
    int idx = blockIdx.x * 256 + threadIdx.x;
    if (idx >= NL * HW) return;
    int w = idx % W;
    int h = (idx / W) % H;
    int n = idx / HW;
    int b = n / L, l = n % L;

    const float* t = nam + (size_t)(b * L * L + l) * 6;
    float gx = (w + 0.5f) * (2.0f / W) - 1.0f;
    float gy = (h + 0.5f) * (2.0f / H) - 1.0f;
    float u = t[0] * gx + t[1] * gy + t[2];
    float v = t[3] * gx + t[4] * gy + t[5];

    float xf = ((u + 1.0f) * (float)W - 1.0f) * 0.5f;
    float yf = ((v + 1.0f) * (float)H - 1.0f) * 0.5f;
    float x0f = floorf(xf), y0f = floorf(yf);
    float wx1 = xf - x0f, wy1 = yf - y0f;
    float wx0 = 1.0f - wx1, wy0 = 1.0f - wy1;
    int x0 = (int)x0f, y0 = (int)y0f;
    int x1 = x0 + 1,  y1 = y0 + 1;

    bool vx0 = (x0 >= 0) && (x0 < W), vx1 = (x1 >= 0) && (x1 < W);
    bool vy0 = (y0 >= 0) && (y0 < H), vy1 = (y1 >= 0) && (y1 < H);
    int cx0 = min(max(x0, 0), W - 1), cx1 = min(max(x1, 0), W - 1);
    int cy0 = min(max(y0, 0), H - 1), cy1 = min(max(y1, 0), H - 1);

    float w00 = wx0 * wy0 * ((vx0 && vy0) ? 1.0f : 0.0f);
    float w10 = wx1 * wy0 * ((vx1 && vy0) ? 1.0f : 0.0f);
    float w01 = wx0 * wy1 * ((vx0 && vy1) ? 1.0f : 0.0f);
    float w11 = wx1 * wy1 * ((vx1 && vy1) ? 1.0f : 0.0f);

    int o00 = cy0 * W + cx0, o10 = cy0 * W + cx1;
    int o01 = cy1 * W + cx0, o11 = cy1 * W + cx1;

    const float* ip = x + (size_t)n * C * HW;
    float* op = g_neigh + (size_t)n * C * HW + h * W + w;
#pragma unroll 4
    for (int c = 0; c < C; c++) {
        const float* pc = ip + (size_t)c * HW;
        float val = pc[o00] * w00 + pc[o10] * w10 + pc[o01] * w01 + pc[o11] * w11;
        op[(size_t)c * HW] = val;
    }
}

// ---------------------------------------------------------------------------
// Weight transpose: [COUT][CIN][4][4] -> [CIN][16][COUT]
// ---------------------------------------------------------------------------
__global__ void wtr_k(const float* __restrict__ src, float* __restrict__ dst,
                      int cin, int cout)
{
    int i = blockIdx.x * 256 + threadIdx.x;
    int tot = cin * cout * 16;
    if (i >= tot) return;
    int co = i / (cin * 16);
    int rr = i % (cin * 16);
    int c  = rr / 16;
    int k  = rr % 16;
    dst[(c * 16 + k) * cout + co] = src[i];
}

// ---------------------------------------------------------------------------
// 2) Direct conv 4x4 stride-2 pad-1, packed f32x2 FMA, smem-tiled.
//    CC kept small so smem/block is ~22-28KB -> 8-10 blocks/SM (occupancy).
// ---------------------------------------------------------------------------
template<int CIN_ALL, int CINBLK, int COUT, int IH, int IW, int OH, int OW,
         int TOH, int TOW, int CC, int COT, int PPT, bool RELU, int NSPLIT>
__global__ void __launch_bounds__((TOH * TOW / PPT) * (COUT / COT))
conv_k(const float* __restrict__ in, const float* __restrict__ wgt,
       const float* __restrict__ bias, float* __restrict__ out)
{
    constexpr int ITH   = 2 * TOH + 2;
    constexpr int ITW   = 2 * TOW + 2;
    constexpr int ITWP  = (ITW + 3) & ~3;
    constexpr int PGRP  = TOH * TOW / PPT;
    constexpr int NGRP  = COUT / COT;
    constexpr int NT    = PGRP * NGRP;
    constexpr int NPAIR = PPT / 2;
    constexpr int NV4   = (2 * PPT + 2 + 3) / 4;

    extern __shared__ float sm[];
    float* s_in = sm;                               // [CC][ITH][ITWP]
    float* s_w  = sm + CC * ITH * ITWP;             // [CC][16][COUT]

    const int bz    = blockIdx.z;
    const int n     = bz / NSPLIT;
    const int split = bz % NSPLIT;
    const int cbase = split * CINBLK;
    const int oh0   = blockIdx.y * TOH;
    const int ow0   = blockIdx.x * TOW;
    const int tid   = threadIdx.x;
    const int pg    = tid % PGRP;
    const int cg    = tid / PGRP;
    const int co0   = cg * COT;
    const int pos0  = pg * PPT;
    const int ohl   = pos0 / TOW;
    const int owb   = pos0 % TOW;

    unsigned long long acc[COT][NPAIR];
#pragma unroll
    for (int a = 0; a < COT; a++)
#pragma unroll
        for (int p = 0; p < NPAIR; p++) acc[a][p] = 0ull;

    for (int c0 = 0; c0 < CINBLK; c0 += CC) {
        __syncthreads();
        // fill input tile (zero-pad OOB)
        for (int i = tid; i < CC * ITH * ITW; i += NT) {
            int c   = i / (ITH * ITW);
            int rem = i % (ITH * ITW);
            int r   = rem / ITW;
            int col = rem % ITW;
            int ih = oh0 * 2 - 1 + r;
            int iw = ow0 * 2 - 1 + col;
            float v = 0.0f;
            if (ih >= 0 && ih < IH && iw >= 0 && iw < IW)
                v = in[((size_t)(n * CIN_ALL + cbase + c0 + c) * IH + ih) * IW + iw];
            s_in[(c * ITH + r) * ITWP + col] = v;
        }
        // fill weight chunk (contiguous in transposed layout)
        {
            const float* wsrc = wgt + (size_t)(cbase + c0) * 16 * COUT;
            for (int i = tid; i < CC * 16 * COUT; i += NT)
                s_w[i] = wsrc[i];
        }
        __syncthreads();

#pragma unroll 1
        for (int c = 0; c < CC; c++) {
            const float* srow = s_in + c * ITH * ITWP;
            const float* swc  = s_w + c * 16 * COUT;
#pragma unroll
            for (int kh = 0; kh < 4; kh++) {
                float rvf[NV4 * 4];
                const float4* rp =
                    (const float4*)(srow + (ohl * 2 + kh) * ITWP + owb * 2);
#pragma unroll
                for (int j = 0; j < NV4; j++) {
                    float4 t = rp[j];
                    rvf[4 * j + 0] = t.x; rvf[4 * j + 1] = t.y;
                    rvf[4 * j + 2] = t.z; rvf[4 * j + 3] = t.w;
                }
#pragma unroll
                for (int kw = 0; kw < 4; kw++) {
                    unsigned long long ivp[NPAIR];
#pragma unroll
                    for (int p = 0; p < NPAIR; p++)
                        ivp[p] = pk2(rvf[4 * p + kw], rvf[4 * p + kw + 2]);
                    const float* swk = swc + (kh * 4 + kw) * COUT + co0;
#pragma unroll
                    for (int a = 0; a < COT; a++) {
                        float wv = swk[a];
                        unsigned long long wd = pk2(wv, wv);
#pragma unroll
                        for (int p = 0; p < NPAIR; p++)
                            fma2(acc[a][p], wd, ivp[p]);
                    }
                }
            }
        }
    }

    const int oh = oh0 + ohl;
#pragma unroll
    for (int a = 0; a < COT; a++) {
        const int co = co0 + a;
        float bb = RELU ? bias[co] : 0.0f;
#pragma unroll
        for (int p = 0; p < NPAIR; p++) {
            float2 v = up2(acc[a][p]);
            size_t idx;
            if (RELU) {
                v.x = fmaxf(v.x + bb, 0.0f);
                v.y = fmaxf(v.y + bb, 0.0f);
                idx = ((size_t)(n * COUT + co) * OH + oh) * OW + ow0 + owb + 2 * p;
            } else {
                idx = ((size_t)((split * NL + n) * COUT + co) * OH + oh) * OW
                      + ow0 + owb + 2 * p;
            }
            *(float2*)&out[idx] = v;
        }
    }
}

// ---------------------------------------------------------------------------
// 3) conv3 partial combine + bias + relu + global average pool (wide grid)
// ---------------------------------------------------------------------------
__global__ void pool_k(const float* __restrict__ bias)
{
    int wid  = (blockIdx.x * blockDim.x + threadIdx.x) >> 5;
    int lane = threadIdx.x & 31;
    if (wid >= NL * 64) return;
    int co = wid % 64;
    float bb = bias[co];
    const float* p = g_c3p + (size_t)wid * 512;
    constexpr size_t SP = (size_t)NL * 64 * 512;
    float s = 0.0f;
    for (int i = lane; i < 512; i += 32) {
        float v = p[i] + p[i + SP] + p[i + 2 * SP] + p[i + 3 * SP] + bb;
        s += fmaxf(v, 0.0f);
    }
#pragma unroll
    for (int o = 16; o; o >>= 1) s += __shfl_xor_sync(0xffffffffu, s, o);
    if (lane == 0) g_pool[wid] = s * (1.0f / 512.0f);
}

// ---------------------------------------------------------------------------
// 4) Tiny FC layers
// ---------------------------------------------------------------------------
template<int IN, int OUT, bool RELU>
__global__ void fc_k(const float* __restrict__ X, int xstride,
                     const float* __restrict__ Wm, const float* __restrict__ bv,
                     float* __restrict__ Y, int rows)
{
    int g = blockIdx.x * blockDim.x + threadIdx.x;
    if (g >= rows * OUT) return;
    int r = g / OUT, o = g % OUT;
    const float* xr = X + (size_t)r * xstride;
    const float* wr = Wm + (size_t)o * IN;
    float s = bv[o];
#pragma unroll 8
    for (int i = 0; i < IN; i++) s = fmaf(xr[i], wr[i], s);
    if (RELU) s = s > 0.0f ? s : 0.0f;
    Y[r * OUT + o] = s;
}

// ---------------------------------------------------------------------------
// 5) Attention logits + softmax
// ---------------------------------------------------------------------------
__global__ void attn_k()
{
    int b    = blockIdx.x;
    int lane = threadIdx.x & 31;
    int wl   = threadIdx.x >> 5;
    __shared__ float lg[L];
    if (wl < L) {
        const float* k = g_keys + (size_t)(b * L + wl) * 256;
        const float* q = g_q + (size_t)b * 256;
        float s = 0.0f;
        for (int i = lane; i < 256; i += 32) s = fmaf(k[i], q[i], s);
#pragma unroll
        for (int o = 16; o; o >>= 1) s += __shfl_xor_sync(0xffffffffu, s, o);
        if (lane == 0) lg[wl] = s;
    }
    __syncthreads();
    if (threadIdx.x == 0) {
        float m = lg[0];
#pragma unroll
        for (int l = 1; l < L; l++) m = fmaxf(m, lg[l]);
        float e[L], sum = 0.0f;
#pragma unroll
        for (int l = 0; l < L; l++) { e[l] = expf(lg[l] - m); sum += e[l]; }
        float inv = 1.0f / sum;
#pragma unroll
        for (int l = 0; l < L; l++) g_attn[b * L + l] = e[l] * inv;
    }
}

// ---------------------------------------------------------------------------
// 6) Fusion (float4 vectorized)
// ---------------------------------------------------------------------------
__global__ void fuse_k(float* __restrict__ out)
{
    int idx = blockIdx.x * 256 + threadIdx.x;       // float4 index
    constexpr int TOT = B * C * HW / 4;
    if (idx >= TOT) return;
    int b = idx / (C * HW / 4);
    int rem = idx - b * (C * HW / 4);
    const float4* np = (const float4*)(g_neigh + (size_t)b * L * C * HW) + rem;
    float4 s = make_float4(0.f, 0.f, 0.f, 0.f);
#pragma unroll
    for (int l = 0; l < L; l++) {
        float a = g_attn[b * L + l];
        float4 v = np[(size_t)l * (C * HW / 4)];
        s.x = fmaf(a, v.x, s.x); s.y = fmaf(a, v.y, s.y);
        s.z = fmaf(a, v.z, s.z); s.w = fmaf(a, v.w, s.w);
    }
    ((float4*)out)[idx] = s;
}

// ---------------------------------------------------------------------------
// Launch
// ---------------------------------------------------------------------------
extern "C" void kernel_launch(void* const* d_in, const int* in_sizes, int n_in,
                              void* d_out, int out_size)
{
    (void)in_sizes; (void)n_in; (void)out_size;
    const float* x    = (const float*)d_in[0];
    const float* nam  = (const float*)d_in[2];
    const float* w1   = (const float*)d_in[3];
    const float* b1   = (const float*)d_in[4];
    const float* w2   = (const float*)d_in[5];
    const float* b2   = (const float*)d_in[6];
    const float* w3   = (const float*)d_in[7];
    const float* b3   = (const float*)d_in[8];
    const float* kf1w = (const float*)d_in[9];
    const float* kf1b = (const float*)d_in[10];
    const float* kf2w = (const float*)d_in[11];
    const float* kf2b = (const float*)d_in[12];
    const float* kf3w = (const float*)d_in[13];
    const float* kf3b = (const float*)d_in[14];
    const float* qf1w = (const float*)d_in[15];
    const float* qf1b = (const float*)d_in[16];
    const float* qf2w = (const float*)d_in[17];
    const float* qf2b = (const float*)d_in[18];
    const float* qf3w = (const float*)d_in[19];
    const float* qf3b = (const float*)d_in[20];
    const float* aw   = (const float*)d_in[21];
    const float* ab   = (const float*)d_in[22];
    float* out = (float*)d_out;

    float *p_neigh, *p_c1, *p_c2, *p_c3p, *p_pool, *p_h1, *p_h2, *p_keys,
          *p_qh1, *p_qh2, *p_qry, *p_q, *p_wt1, *p_wt2, *p_wt3;
    cudaGetSymbolAddress((void**)&p_neigh, g_neigh);
    cudaGetSymbolAddress((void**)&p_c1,   g_c1);
    cudaGetSymbolAddress((void**)&p_c2,   g_c2);
    cudaGetSymbolAddress((void**)&p_c3p,  g_c3p);
    cudaGetSymbolAddress((void**)&p_pool, g_pool);
    cudaGetSymbolAddress((void**)&p_h1,   g_h1);
    cudaGetSymbolAddress((void**)&p_h2,   g_h2);
    cudaGetSymbolAddress((void**)&p_keys, g_keys);
    cudaGetSymbolAddress((void**)&p_qh1,  g_qh1);
    cudaGetSymbolAddress((void**)&p_qh2,  g_qh2);
    cudaGetSymbolAddress((void**)&p_qry,  g_qry);
    cudaGetSymbolAddress((void**)&p_q,    g_q);
    cudaGetSymbolAddress((void**)&p_wt1,  g_wt1);
    cudaGetSymbolAddress((void**)&p_wt2,  g_wt2);
    cudaGetSymbolAddress((void**)&p_wt3,  g_wt3);

    // conv kernel instantiations — CC=4 for occupancy (8-10 blocks/SM)
    auto c1 = conv_k<64, 64, 32, 256, 128, 128, 64, 16, 16, 4, 8, 8, true, 1>;
    auto c2 = conv_k<32, 32, 64, 128, 64, 64, 32, 8, 8, 4, 4, 8, true, 1>;
    auto c3 = conv_k<64, 16, 64, 64, 32, 32, 16, 4, 16, 4, 4, 8, false, KSPLIT3>;
    const int sm1 = (4 * 34 * 36 + 4 * 16 * 32) * 4;   // 27776
    const int sm2 = (4 * 18 * 20 + 4 * 16 * 64) * 4;   // 22144
    const int sm3 = (4 * 10 * 36 + 4 * 16 * 64) * 4;   // 22144
    cudaFuncSetAttribute(c1, cudaFuncAttributeMaxDynamicSharedMemorySize, sm1);
    cudaFuncSetAttribute(c2, cudaFuncAttributeMaxDynamicSharedMemorySize, sm2);
    cudaFuncSetAttribute(c3, cudaFuncAttributeMaxDynamicSharedMemorySize, sm3);

    // 0) weight transposes (tiny)
    wtr_k<<<(C * C1O * 16 + 255) / 256, 256>>>(w1, p_wt1, C, C1O);
    wtr_k<<<(C1O * C2O * 16 + 255) / 256, 256>>>(w2, p_wt2, C1O, C2O);
    wtr_k<<<(C2O * C3O * 16 + 255) / 256, 256>>>(w3, p_wt3, C2O, C3O);

    // 1) grid sample
    sample_k<<<(NL * HW + 255) / 256, 256>>>(x, nam);

    // 2) conv pyramid
    c1<<<dim3(W1 / 16, H1 / 16, NL), 128, sm1>>>(p_neigh, p_wt1, b1, p_c1);
    c2<<<dim3(W2 / 8,  H2 / 8,  NL), 128, sm2>>>(p_c1,    p_wt2, b2, p_c2);
    c3<<<dim3(W3 / 16, H3 / 4,  NL * KSPLIT3), 128, sm3>>>(p_c2, p_wt3, b3, p_c3p);

    // 3) combine + pool (wide grid)
    pool_k<<<(NL * 64 * 32 + 255) / 256, 256>>>(b3);

    // 4) key head (rows = 20)
    fc_k<64, 256, true ><<<(NL * 256 + 255) / 256, 256>>>(p_pool, 64,  kf1w, kf1b, p_h1, NL);
    fc_k<256, 128, true><<<(NL * 128 + 255) / 256, 256>>>(p_h1, 256, kf2w, kf2b, p_h2, NL);
    fc_k<128, 256, false><<<(NL * 256 + 255) / 256, 256>>>(p_h2, 128, kf3w, kf3b, p_keys, NL);

    //    query head (rows = 4)
    fc_k<64, 256, true ><<<(B * 256 + 255) / 256, 256>>>(p_pool, L * 64, qf1w, qf1b, p_qh1, B);
    fc_k<256, 128, true><<<(B * 128 + 255) / 256, 256>>>(p_qh1, 256, qf2w, qf2b, p_qh2, B);
    fc_k<128, 32, false><<<1, 128>>>(p_qh2, 128, qf3w, qf3b, p_qry, B);
    fc_k<32, 256, false><<<(B * 256 + 255) / 256, 256>>>(p_qry, 32, aw, ab, p_q, B);

    // 5) attention softmax
    attn_k<<<B, 192>>>();

    // 6) fuse
    fuse_k<<<(B * C * HW / 4 + 255) / 256, 256>>>(out);
}